// round 13
// baseline (speedup 1.0000x reference)
#include <cuda_runtime.h>
#include <cuda_fp16.h>
#include <cstdint>

#define B_   16
#define S_   512
#define H_   128
#define L_   20
#define TM   128          // s per CTA
#define TT   32           // t per CTA
#define NCHUNKS 8         // 4 t x 20 l = 80 N rows per chunk
#define NROWS 80
#define STRDH 136         // smem row stride (halves): 272B, conflict-free ldmatrix
#define R1STR 22          // r1 smem stride (floats)
#define NTHR 128          // 4 warps: wm=2 (64 rows), wn=2 (40 cols)

// smem halves layout
#define NH_A   (TM * STRDH)            // 17408
#define NH_BUF (NROWS * STRDH)         // 10880 per buffer
#define OFFH_B0 NH_A
#define OFFH_B1 (NH_A + NH_BUF)
#define OFFH_R1 (NH_A + 2 * NH_BUF)    // 39168 halves -> byte 78336 (16-aligned)
#define SMEM_BYTES (OFFH_R1 * 2 + TM * R1STR * 4)   // 89600 -> 2 CTAs/SM

// precomputed operands in HBM
__device__ __half g_A[B_ * S_ * H_];              // fp16(v1)                2 MB
__device__ __half g_B[(size_t)B_ * S_ * L_ * H_]; // fp16(v2 * w^2 * r2)  41.9 MB
__device__ float  g_r1[B_ * L_ * S_];

static __device__ __forceinline__ uint32_t f16x2(float lo, float hi) {
    uint32_t r;
    asm("cvt.rn.f16x2.f32 %0, %1, %2;" : "=r"(r) : "f"(hi), "f"(lo));
    return r;
}
static __device__ __forceinline__ void mma_f16(float& c0, float& c1, float& c2, float& c3,
                                               uint32_t a0, uint32_t a1, uint32_t a2, uint32_t a3,
                                               uint32_t b0, uint32_t b1) {
    asm volatile("mma.sync.aligned.m16n8k16.row.col.f32.f16.f16.f32 "
                 "{%0,%1,%2,%3}, {%4,%5,%6,%7}, {%8,%9}, {%0,%1,%2,%3};"
                 : "+f"(c0), "+f"(c1), "+f"(c2), "+f"(c3)
                 : "r"(a0), "r"(a1), "r"(a2), "r"(a3), "r"(b0), "r"(b1));
}
static __device__ __forceinline__ void ldsm4(uint32_t& r0, uint32_t& r1, uint32_t& r2, uint32_t& r3,
                                             uint32_t addr) {
    asm volatile("ldmatrix.sync.aligned.m8n8.x4.shared.b16 {%0,%1,%2,%3}, [%4];"
                 : "=r"(r0), "=r"(r1), "=r"(r2), "=r"(r3) : "r"(addr));
}
static __device__ __forceinline__ void ldsm2(uint32_t& r0, uint32_t& r1, uint32_t addr) {
    asm volatile("ldmatrix.sync.aligned.m8n8.x2.shared.b16 {%0,%1}, [%2];"
                 : "=r"(r0), "=r"(r1) : "r"(addr));
}
static __device__ __forceinline__ uint32_t smem_u32(const void* p) {
    return (uint32_t)__cvta_generic_to_shared(p);
}
static __device__ __forceinline__ void cp16(uint32_t dst, const void* src) {
    asm volatile("cp.async.ca.shared.global [%0], [%1], 16;" :: "r"(dst), "l"(src) : "memory");
}
#define CP_COMMIT() asm volatile("cp.async.commit_group;" ::: "memory")
#define CP_WAIT1()  asm volatile("cp.async.wait_group 1;" ::: "memory")
#define CP_WAIT0()  asm volatile("cp.async.wait_group 0;" ::: "memory")

// ---------------- kernel 1: norms + operand prep (fused) ----------------
__global__ void prep_kernel(const float* __restrict__ v1, const float* __restrict__ v2,
                            const float* __restrict__ w) {
    const int which = blockIdx.y;
    const float* v  = which ? v2 : v1;
    const int gwarp = (blockIdx.x * blockDim.x + threadIdx.x) >> 5;
    const int lane  = threadIdx.x & 31;
    if (gwarp >= B_ * S_) return;

    const float4 xv = ((const float4*)(v + (size_t)gwarp * H_))[lane];

    if (!which) {   // fp16(v1) row
        uint2 o;
        o.x = f16x2(xv.x, xv.y);
        o.y = f16x2(xv.z, xv.w);
        *(uint2*)&g_A[(size_t)gwarp * H_ + lane * 4] = o;
    }
    const int b = gwarp >> 9;
    const int s = gwarp & (S_ - 1);

    #pragma unroll
    for (int l = 0; l < L_; l += 2) {
        const float4 w0 = ((const float4*)(w + l * H_))[lane];
        const float4 w1 = ((const float4*)(w + (l + 1) * H_))[lane];
        float t, p0, p1;
        t = w0.x * xv.x; p0  = t * t;  t = w1.x * xv.x; p1  = t * t;
        t = w0.y * xv.y; p0 += t * t;  t = w1.y * xv.y; p1 += t * t;
        t = w0.z * xv.z; p0 += t * t;  t = w1.z * xv.z; p1 += t * t;
        t = w0.w * xv.w; p0 += t * t;  t = w1.w * xv.w; p1 += t * t;
        #pragma unroll
        for (int o = 16; o; o >>= 1) {
            p0 += __shfl_xor_sync(0xffffffffu, p0, o);
            p1 += __shfl_xor_sync(0xffffffffu, p1, o);
        }
        const float ra = rsqrtf(fmaxf(p0, 1e-24f));
        const float rb = rsqrtf(fmaxf(p1, 1e-24f));
        if (!which) {
            if (lane == 0) {
                g_r1[((size_t)b * L_ + l) * S_ + s]     = ra;
                g_r1[((size_t)b * L_ + l + 1) * S_ + s] = rb;
            }
        } else {
            uint2 oa, ob;
            oa.x = f16x2(xv.x * w0.x * w0.x * ra, xv.y * w0.y * w0.y * ra);
            oa.y = f16x2(xv.z * w0.z * w0.z * ra, xv.w * w0.w * w0.w * ra);
            ob.x = f16x2(xv.x * w1.x * w1.x * rb, xv.y * w1.y * w1.y * rb);
            ob.y = f16x2(xv.z * w1.z * w1.z * rb, xv.w * w1.w * w1.w * rb);
            *(uint2*)&g_B[((size_t)gwarp * L_ + l) * H_ + lane * 4]     = oa;
            *(uint2*)&g_B[((size_t)gwarp * L_ + l + 1) * H_ + lane * 4] = ob;
        }
    }
}

// ---------------- kernel 2: fp16 GEMM, 128 thr, 64x40 warp tiles ----------------
// 4 warps: warp_m = wid>>1 (2 x 64 rows = 4 m16), warp_n = wid&1 (2 x 40 cols = 5 n8).
// B smem reads deduplicated 4x -> 2x vs the 32x40 tiling.
__global__ void __launch_bounds__(NTHR, 2)
match_kernel(float* __restrict__ out) {
    extern __shared__ char smc[];
    __half* sm  = (__half*)smc;
    float*  sR1 = (float*)(smc + OFFH_R1 * 2);   // [128][R1STR] r1 transposed

    const int tid  = threadIdx.x;
    const int wid  = tid >> 5;
    const int lane = tid & 31;
    const int b    = blockIdx.z;
    const int s0   = blockIdx.x * TM;            // s fastest: co-resident CTAs share B in L2
    const int t0   = blockIdx.y * TT;

    const int warp_m = wid >> 1;   // 0..1 (64 rows each)
    const int warp_n = wid & 1;    // 0..1 (40 cols each)
    const int grp    = lane >> 2;  // 0..7
    const int thr4   = lane & 3;   // 0..3

    const uint32_t sm_u = smem_u32(sm);
    const __half* gA = g_A + ((size_t)b * S_ + s0) * H_;

    // ---- cp.async: A tile (with chunk 0 in group 0) ----
    #pragma unroll
    for (int k = 0; k < 16; ++k) {
        const int task = tid + k * NTHR;         // 2048 x 16B
        const int r = task >> 4, seg = task & 15;
        cp16(sm_u + (uint32_t)(r * STRDH + seg * 8) * 2u, gA + r * H_ + seg * 8);
    }
    auto issue_chunk = [&](int c, int buf) {
        const __half* src = g_B + (size_t)(b * S_ + t0 + c * 4) * L_ * H_;   // 80 contiguous rows
        const uint32_t dst = sm_u + (uint32_t)(buf ? OFFH_B1 : OFFH_B0) * 2u;
        #pragma unroll
        for (int k = 0; k < 10; ++k) {
            const int task = tid + k * NTHR;     // 1280 x 16B
            const int r = task >> 4, seg = task & 15;
            cp16(dst + (uint32_t)(r * STRDH + seg * 8) * 2u, src + r * H_ + seg * 8);
        }
    };
    issue_chunk(0, 0);
    CP_COMMIT();                                  // group 0 = A + chunk0
    issue_chunk(1, 1);
    CP_COMMIT();                                  // group 1 = chunk1

    // r1 -> smem transposed [row][l]
    for (int i = tid; i < TM * L_; i += NTHR) {
        const int l = i >> 7, r = i & 127;
        sR1[r * R1STR + l] = g_r1[((size_t)b * L_ + l) * S_ + s0 + r];
    }

    // ldmatrix base addresses: 4 A m16-tiles per warp
    uint32_t a_base[4];
    #pragma unroll
    for (int i = 0; i < 4; ++i) {
        const int row = warp_m * 64 + i * 16 + (lane & 15);
        a_base[i] = sm_u + (uint32_t)(row * STRDH + ((lane >> 4) << 3)) * 2u;
    }
    uint32_t b_off[2];
    #pragma unroll
    for (int jp = 0; jp < 2; ++jp) {
        const int row = warp_n * 40 + jp * 16 + (lane & 7) + ((lane >> 4) << 3);
        b_off[jp] = (uint32_t)(row * STRDH + (((lane >> 3) & 1) << 3)) * 2u;
    }
    const uint32_t b_off4 =
        (uint32_t)((warp_n * 40 + 32 + (lane & 7)) * STRDH + (((lane >> 3) & 1) << 3)) * 2u;
    const uint32_t bufu[2] = { sm_u + (uint32_t)OFFH_B0 * 2u, sm_u + (uint32_t)OFFH_B1 * 2u };

    const size_t bS = (size_t)b * S_;

    #pragma unroll 1
    for (int chunk = 0; chunk < NCHUNKS; ++chunk) {
        if (chunk == NCHUNKS - 1) { CP_WAIT0(); } else { CP_WAIT1(); }
        __syncthreads();

        const uint32_t bb = bufu[chunk & 1];
        float acc[4][5][4];
        #pragma unroll
        for (int i = 0; i < 4; ++i)
            #pragma unroll
            for (int j = 0; j < 5; ++j)
                #pragma unroll
                for (int q = 0; q < 4; ++q) acc[i][j][q] = 0.f;

        #pragma unroll
        for (int k16 = 0; k16 < 8; ++k16) {
            const uint32_t koff = (uint32_t)(k16 * 32);
            uint32_t bf[5][2];
            ldsm4(bf[0][0], bf[0][1], bf[1][0], bf[1][1], bb + b_off[0] + koff);
            ldsm4(bf[2][0], bf[2][1], bf[3][0], bf[3][1], bb + b_off[1] + koff);
            ldsm2(bf[4][0], bf[4][1], bb + b_off4 + koff);
            uint32_t af[4][4];
            #pragma unroll
            for (int i = 0; i < 4; ++i)
                ldsm4(af[i][0], af[i][1], af[i][2], af[i][3], a_base[i] + koff);
            #pragma unroll
            for (int i = 0; i < 4; ++i)
                #pragma unroll
                for (int j = 0; j < 5; ++j)
                    mma_f16(acc[i][j][0], acc[i][j][1], acc[i][j][2], acc[i][j][3],
                            af[i][0], af[i][1], af[i][2], af[i][3], bf[j][0], bf[j][1]);
        }

        // ---- epilogue: out = acc * r1[l,row] ----
        #pragma unroll
        for (int i = 0; i < 4; ++i) {
            const int rowl = warp_m * 64 + i * 16 + grp;
            float* orow0 = out + ((bS + s0 + rowl) * S_ + t0 + chunk * 4) * L_;
            float* orow1 = orow0 + (size_t)8 * S_ * L_;
            #pragma unroll
            for (int j = 0; j < 5; ++j) {
                const int c = warp_n * 40 + j * 8 + 2 * thr4;  // in [0,80); c = ts*20 + l
                const int ts = c / 20;
                const int l  = c - ts * 20;
                (void)ts;
                const float2 ra = *(const float2*)&sR1[rowl * R1STR + l];
                const float2 rb = *(const float2*)&sR1[(rowl + 8) * R1STR + l];
                float2 v0, v1r;
                v0.x  = acc[i][j][0] * ra.x;  v0.y  = acc[i][j][1] * ra.y;
                v1r.x = acc[i][j][2] * rb.x;  v1r.y = acc[i][j][3] * rb.y;
                *(float2*)(orow0 + c) = v0;    // out offset within row == c
                *(float2*)(orow1 + c) = v1r;
            }
        }
        __syncthreads();

        if (chunk + 2 < NCHUNKS) {
            issue_chunk(chunk + 2, chunk & 1);
            CP_COMMIT();
        }
    }
}

// ---------------- launch ----------------
extern "C" void kernel_launch(void* const* d_in, const int* in_sizes, int n_in,
                              void* d_out, int out_size) {
    (void)in_sizes; (void)n_in; (void)out_size;
    const float* v1 = (const float*)d_in[0];   // (16, 512, 128)
    const float* v2 = (const float*)d_in[1];   // (16, 512, 128)
    const float* w  = (const float*)d_in[2];   // (20, 128)
    float* out = (float*)d_out;                // (16, 512, 512, 20)

    cudaFuncSetAttribute(match_kernel, cudaFuncAttributeMaxDynamicSharedMemorySize, SMEM_BYTES);

    dim3 pgrid((B_ * S_ * 32) / 256, 2);       // y=0: v1/r1/A, y=1: v2 -> B
    prep_kernel<<<pgrid, 256>>>(v1, v2, w);

    dim3 grid(S_ / TM, S_ / TT, B_);           // (4, 16, 16) = 1024 CTAs; s fastest
    match_kernel<<<grid, NTHR, SMEM_BYTES>>>(out);
}

// round 14
// speedup vs baseline: 1.0801x; 1.0801x over previous
#include <cuda_runtime.h>
#include <cuda_fp16.h>
#include <cstdint>

#define B_   16
#define S_   512
#define H_   128
#define L_   20
#define TM   128          // s per CTA
#define TT   32           // t per CTA  (2 CTAs per SM)
#define NCHUNKS 8         // 4 t x 20 l = 80 N rows per chunk
#define NROWS 80
#define STRDH 136         // smem row stride (halves): 272B, conflict-free ldmatrix
#define R1STR 22          // r1 smem stride (floats)
#define CSTR 88           // C staging row stride (floats): banks 0/24/16/8 tile

// smem halves layout (B buffers enlarged to hold 64x88 fp32 staging overlay)
#define NH_A   (TM * STRDH)            // 17408
#define NH_BUF 11264                   // 22528 B >= max(80*136*2, 64*88*4)
#define OFFH_B0 NH_A
#define OFFH_B1 (NH_A + NH_BUF)
#define OFFH_R1 (NH_A + 2 * NH_BUF)    // 39936 halves -> byte 79872 (16-aligned)
#define SMEM_BYTES (OFFH_R1 * 2 + TM * R1STR * 4)   // 79872 + 11264 = 91136

// precomputed operands in HBM
__device__ __half g_A[B_ * S_ * H_];              // fp16(v1)                2 MB
__device__ __half g_B[(size_t)B_ * S_ * L_ * H_]; // fp16(v2 * w^2 * r2)  41.9 MB
__device__ float  g_r1[B_ * L_ * S_];

static __device__ __forceinline__ uint32_t f16x2(float lo, float hi) {
    uint32_t r;
    asm("cvt.rn.f16x2.f32 %0, %1, %2;" : "=r"(r) : "f"(hi), "f"(lo));
    return r;
}
static __device__ __forceinline__ void mma_f16(float& c0, float& c1, float& c2, float& c3,
                                               uint32_t a0, uint32_t a1, uint32_t a2, uint32_t a3,
                                               uint32_t b0, uint32_t b1) {
    asm volatile("mma.sync.aligned.m16n8k16.row.col.f32.f16.f16.f32 "
                 "{%0,%1,%2,%3}, {%4,%5,%6,%7}, {%8,%9}, {%0,%1,%2,%3};"
                 : "+f"(c0), "+f"(c1), "+f"(c2), "+f"(c3)
                 : "r"(a0), "r"(a1), "r"(a2), "r"(a3), "r"(b0), "r"(b1));
}
static __device__ __forceinline__ void ldsm4(uint32_t& r0, uint32_t& r1, uint32_t& r2, uint32_t& r3,
                                             uint32_t addr) {
    asm volatile("ldmatrix.sync.aligned.m8n8.x4.shared.b16 {%0,%1,%2,%3}, [%4];"
                 : "=r"(r0), "=r"(r1), "=r"(r2), "=r"(r3) : "r"(addr));
}
static __device__ __forceinline__ void ldsm2(uint32_t& r0, uint32_t& r1, uint32_t addr) {
    asm volatile("ldmatrix.sync.aligned.m8n8.x2.shared.b16 {%0,%1}, [%2];"
                 : "=r"(r0), "=r"(r1) : "r"(addr));
}
static __device__ __forceinline__ uint32_t smem_u32(const void* p) {
    return (uint32_t)__cvta_generic_to_shared(p);
}
static __device__ __forceinline__ void cp16(uint32_t dst, const void* src) {
    asm volatile("cp.async.ca.shared.global [%0], [%1], 16;" :: "r"(dst), "l"(src) : "memory");
}
#define CP_COMMIT() asm volatile("cp.async.commit_group;" ::: "memory")
#define CP_WAIT1()  asm volatile("cp.async.wait_group 1;" ::: "memory")
#define CP_WAIT0()  asm volatile("cp.async.wait_group 0;" ::: "memory")

// ---------------- kernel 1: norms + operand prep (fused) ----------------
__global__ void prep_kernel(const float* __restrict__ v1, const float* __restrict__ v2,
                            const float* __restrict__ w) {
    const int which = blockIdx.y;
    const float* v  = which ? v2 : v1;
    const int gwarp = (blockIdx.x * blockDim.x + threadIdx.x) >> 5;
    const int lane  = threadIdx.x & 31;
    if (gwarp >= B_ * S_) return;

    const float4 xv = ((const float4*)(v + (size_t)gwarp * H_))[lane];

    if (!which) {   // fp16(v1) row
        uint2 o;
        o.x = f16x2(xv.x, xv.y);
        o.y = f16x2(xv.z, xv.w);
        *(uint2*)&g_A[(size_t)gwarp * H_ + lane * 4] = o;
    }
    const int b = gwarp >> 9;
    const int s = gwarp & (S_ - 1);

    #pragma unroll
    for (int l = 0; l < L_; l += 2) {
        const float4 w0 = ((const float4*)(w + l * H_))[lane];
        const float4 w1 = ((const float4*)(w + (l + 1) * H_))[lane];
        float t, p0, p1;
        t = w0.x * xv.x; p0  = t * t;  t = w1.x * xv.x; p1  = t * t;
        t = w0.y * xv.y; p0 += t * t;  t = w1.y * xv.y; p1 += t * t;
        t = w0.z * xv.z; p0 += t * t;  t = w1.z * xv.z; p1 += t * t;
        t = w0.w * xv.w; p0 += t * t;  t = w1.w * xv.w; p1 += t * t;
        #pragma unroll
        for (int o = 16; o; o >>= 1) {
            p0 += __shfl_xor_sync(0xffffffffu, p0, o);
            p1 += __shfl_xor_sync(0xffffffffu, p1, o);
        }
        const float ra = rsqrtf(fmaxf(p0, 1e-24f));
        const float rb = rsqrtf(fmaxf(p1, 1e-24f));
        if (!which) {
            if (lane == 0) {
                g_r1[((size_t)b * L_ + l) * S_ + s]     = ra;
                g_r1[((size_t)b * L_ + l + 1) * S_ + s] = rb;
            }
        } else {
            uint2 oa, ob;
            oa.x = f16x2(xv.x * w0.x * w0.x * ra, xv.y * w0.y * w0.y * ra);
            oa.y = f16x2(xv.z * w0.z * w0.z * ra, xv.w * w0.w * w0.w * ra);
            ob.x = f16x2(xv.x * w1.x * w1.x * rb, xv.y * w1.y * w1.y * rb);
            ob.y = f16x2(xv.z * w1.z * w1.z * rb, xv.w * w1.w * w1.w * rb);
            *(uint2*)&g_B[((size_t)gwarp * L_ + l) * H_ + lane * 4]     = oa;
            *(uint2*)&g_B[((size_t)gwarp * L_ + l + 1) * H_ + lane * 4] = ob;
        }
    }
}

// ---------------- kernel 2: fp16 GEMM, staged coalesced stores ----------------
// 8 warps: warp_m = wid>>1 (4 x 32 rows), warp_n = wid&1 (2 x 40 cols).
// Epilogue: scale, STS into the DEAD current-B buffer (64x88 f32 overlay,
// conflict-free), then cooperative 320B-contiguous STG.128 drains.
__global__ void __launch_bounds__(256, 2)
match_kernel(float* __restrict__ out) {
    extern __shared__ char smc[];
    __half* sm  = (__half*)smc;
    float*  sR1 = (float*)(smc + OFFH_R1 * 2);   // [128][R1STR] r1 transposed

    const int tid  = threadIdx.x;
    const int wid  = tid >> 5;
    const int lane = tid & 31;
    const int b    = blockIdx.z;
    const int s0   = blockIdx.x * TM;            // s fastest: co-resident CTAs share B in L2
    const int t0   = blockIdx.y * TT;

    const int warp_m = wid >> 1;   // 0..3
    const int warp_n = wid & 1;    // 0..1
    const int grp    = lane >> 2;  // 0..7
    const int thr4   = lane & 3;   // 0..3

    const uint32_t sm_u = smem_u32(sm);
    const __half* gA = g_A + ((size_t)b * S_ + s0) * H_;

    // ---- cp.async: A tile (with chunk 0 in group 0) ----
    #pragma unroll
    for (int k = 0; k < 8; ++k) {
        const int task = tid + k * 256;          // 2048 x 16B
        const int r = task >> 4, seg = task & 15;
        cp16(sm_u + (uint32_t)(r * STRDH + seg * 8) * 2u, gA + r * H_ + seg * 8);
    }
    auto issue_chunk = [&](int c, int buf) {
        const __half* src = g_B + (size_t)(b * S_ + t0 + c * 4) * L_ * H_;   // 80 contiguous rows
        const uint32_t dst = sm_u + (uint32_t)(buf ? OFFH_B1 : OFFH_B0) * 2u;
        #pragma unroll
        for (int k = 0; k < 5; ++k) {
            const int task = tid + k * 256;      // 1280 x 16B
            const int r = task >> 4, seg = task & 15;
            cp16(dst + (uint32_t)(r * STRDH + seg * 8) * 2u, src + r * H_ + seg * 8);
        }
    };
    issue_chunk(0, 0);
    CP_COMMIT();                                  // group 0 = A + chunk0
    issue_chunk(1, 1);
    CP_COMMIT();                                  // group 1 = chunk1

    // r1 -> smem transposed [row][l]
    for (int i = tid; i < TM * L_; i += 256) {
        const int l = i >> 7, r = i & 127;
        sR1[r * R1STR + l] = g_r1[((size_t)b * L_ + l) * S_ + s0 + r];
    }

    // ldmatrix base addresses
    uint32_t a_base[2];
    #pragma unroll
    for (int i = 0; i < 2; ++i) {
        const int row = warp_m * 32 + i * 16 + (lane & 15);
        a_base[i] = sm_u + (uint32_t)(row * STRDH + ((lane >> 4) << 3)) * 2u;
    }
    uint32_t b_off[2];
    #pragma unroll
    for (int jp = 0; jp < 2; ++jp) {
        const int row = warp_n * 40 + jp * 16 + (lane & 7) + ((lane >> 4) << 3);
        b_off[jp] = (uint32_t)(row * STRDH + (((lane >> 3) & 1) << 3)) * 2u;
    }
    const uint32_t b_off4 =
        (uint32_t)((warp_n * 40 + 32 + (lane & 7)) * STRDH + (((lane >> 3) & 1) << 3)) * 2u;
    const uint32_t bufu[2] = { sm_u + (uint32_t)OFFH_B0 * 2u, sm_u + (uint32_t)OFFH_B1 * 2u };

    const size_t bS = (size_t)b * S_;

    #pragma unroll 1
    for (int chunk = 0; chunk < NCHUNKS; ++chunk) {
        if (chunk == NCHUNKS - 1) { CP_WAIT0(); } else { CP_WAIT1(); }
        __syncthreads();

        const uint32_t bb = bufu[chunk & 1];
        float acc[2][5][4];
        #pragma unroll
        for (int i = 0; i < 2; ++i)
            #pragma unroll
            for (int j = 0; j < 5; ++j)
                #pragma unroll
                for (int q = 0; q < 4; ++q) acc[i][j][q] = 0.f;

        #pragma unroll
        for (int k16 = 0; k16 < 8; ++k16) {
            const uint32_t koff = (uint32_t)(k16 * 32);
            uint32_t af[2][4];
            ldsm4(af[0][0], af[0][1], af[0][2], af[0][3], a_base[0] + koff);
            ldsm4(af[1][0], af[1][1], af[1][2], af[1][3], a_base[1] + koff);
            uint32_t bf[5][2];
            ldsm4(bf[0][0], bf[0][1], bf[1][0], bf[1][1], bb + b_off[0] + koff);
            ldsm4(bf[2][0], bf[2][1], bf[3][0], bf[3][1], bb + b_off[1] + koff);
            ldsm2(bf[4][0], bf[4][1], bb + b_off4 + koff);
            #pragma unroll
            for (int i = 0; i < 2; ++i)
                #pragma unroll
                for (int j = 0; j < 5; ++j)
                    mma_f16(acc[i][j][0], acc[i][j][1], acc[i][j][2], acc[i][j][3],
                            af[i][0], af[i][1], af[i][2], af[i][3], bf[j][0], bf[j][1]);
        }
        __syncthreads();   // all reads of bb done -> buffer reusable as C stage

        // ---- staged epilogue: two 64-row halves through the dead bb region ----
        float* cs = (float*)(smc + (size_t)(OFFH_B0 + (chunk & 1) * NH_BUF) * 2);
        #pragma unroll
        for (int h = 0; h < 2; ++h) {
            if ((warp_m >> 1) == h) {            // warp_m {0,1}->h0, {2,3}->h1
                #pragma unroll
                for (int i = 0; i < 2; ++i) {
                    const int rowl = warp_m * 32 + i * 16 + grp;   // global row
                    const int srow = rowl & 63;                    // row within half
                    #pragma unroll
                    for (int j = 0; j < 5; ++j) {
                        const int c = warp_n * 40 + j * 8 + 2 * thr4;  // c = ts*20 + l
                        const int l = c - (c / 20) * 20;               // even
                        const float2 ra = *(const float2*)&sR1[rowl * R1STR + l];
                        const float2 rb = *(const float2*)&sR1[(rowl + 8) * R1STR + l];
                        float2 v0, v1r;
                        v0.x  = acc[i][j][0] * ra.x;  v0.y  = acc[i][j][1] * ra.y;
                        v1r.x = acc[i][j][2] * rb.x;  v1r.y = acc[i][j][3] * rb.y;
                        *(float2*)(cs + srow * CSTR + c)       = v0;
                        *(float2*)(cs + (srow + 8) * CSTR + c) = v1r;
                    }
                }
            }
            __syncthreads();                     // half staged
            // drain: 64 rows x 80 floats, 320B contiguous per gmem row
            float* gbase = out + ((bS + s0 + h * 64) * S_ + t0 + chunk * 4) * L_;
            #pragma unroll
            for (int k = 0; k < 5; ++k) {
                const int task = tid + k * 256;  // 1280 float4 tasks
                const int row  = task / 20;
                const int q    = task - row * 20;
                const float4 v = *(const float4*)(cs + row * CSTR + q * 4);
                *(float4*)(gbase + (size_t)row * S_ * L_ + q * 4) = v;
            }
            __syncthreads();                     // drain done; cs free for next half
        }

        if (chunk + 2 < NCHUNKS) {
            issue_chunk(chunk + 2, chunk & 1);   // safe: staging fully drained
            CP_COMMIT();
        }
    }
}

// ---------------- launch ----------------
extern "C" void kernel_launch(void* const* d_in, const int* in_sizes, int n_in,
                              void* d_out, int out_size) {
    (void)in_sizes; (void)n_in; (void)out_size;
    const float* v1 = (const float*)d_in[0];   // (16, 512, 128)
    const float* v2 = (const float*)d_in[1];   // (16, 512, 128)
    const float* w  = (const float*)d_in[2];   // (20, 128)
    float* out = (float*)d_out;                // (16, 512, 512, 20)

    cudaFuncSetAttribute(match_kernel, cudaFuncAttributeMaxDynamicSharedMemorySize, SMEM_BYTES);

    dim3 pgrid((B_ * S_ * 32) / 256, 2);       // y=0: v1/r1/A, y=1: v2 -> B
    prep_kernel<<<pgrid, 256>>>(v1, v2, w);

    dim3 grid(S_ / TM, S_ / TT, B_);           // (4, 16, 16) = 1024 CTAs; s fastest
    match_kernel<<<grid, 256, SMEM_BYTES>>>(out);
}

// round 15
// speedup vs baseline: 1.1982x; 1.1094x over previous
#include <cuda_runtime.h>
#include <cuda_fp16.h>
#include <cstdint>

#define B_   16
#define S_   512
#define H_   128
#define L_   20
#define TM   128          // s per CTA
#define TT   32           // t per CTA  (2 CTAs per SM)
#define NCHUNKS 8         // 4 t x 20 l = 80 N rows per chunk
#define NROWS 80
#define STRDH 136         // smem row stride (halves): 272B, conflict-free ldmatrix
#define R1STR 22          // r1 smem stride (floats)

// smem halves layout: A + 3-deep B ring + r1
#define NH_A   (TM * STRDH)            // 17408
#define NH_BUF (NROWS * STRDH)         // 10880 per buffer
#define OFFH_B0 NH_A
#define OFFH_R1 (NH_A + 3 * NH_BUF)    // 50048 halves -> byte 100096 (16-aligned)
#define SMEM_BYTES (OFFH_R1 * 2 + TM * R1STR * 4)   // 100096 + 11264 = 111360 -> 2 CTAs/SM

// precomputed operands in HBM
__device__ __half g_A[B_ * S_ * H_];              // fp16(v1)                2 MB
__device__ __half g_B[(size_t)B_ * S_ * L_ * H_]; // fp16(v2 * w^2 * r2)  41.9 MB
__device__ float  g_r1[B_ * L_ * S_];

static __device__ __forceinline__ uint32_t f16x2(float lo, float hi) {
    uint32_t r;
    asm("cvt.rn.f16x2.f32 %0, %1, %2;" : "=r"(r) : "f"(hi), "f"(lo));
    return r;
}
static __device__ __forceinline__ void mma_f16(float& c0, float& c1, float& c2, float& c3,
                                               uint32_t a0, uint32_t a1, uint32_t a2, uint32_t a3,
                                               uint32_t b0, uint32_t b1) {
    asm volatile("mma.sync.aligned.m16n8k16.row.col.f32.f16.f16.f32 "
                 "{%0,%1,%2,%3}, {%4,%5,%6,%7}, {%8,%9}, {%0,%1,%2,%3};"
                 : "+f"(c0), "+f"(c1), "+f"(c2), "+f"(c3)
                 : "r"(a0), "r"(a1), "r"(a2), "r"(a3), "r"(b0), "r"(b1));
}
static __device__ __forceinline__ void ldsm4(uint32_t& r0, uint32_t& r1, uint32_t& r2, uint32_t& r3,
                                             uint32_t addr) {
    asm volatile("ldmatrix.sync.aligned.m8n8.x4.shared.b16 {%0,%1,%2,%3}, [%4];"
                 : "=r"(r0), "=r"(r1), "=r"(r2), "=r"(r3) : "r"(addr));
}
static __device__ __forceinline__ void ldsm2(uint32_t& r0, uint32_t& r1, uint32_t addr) {
    asm volatile("ldmatrix.sync.aligned.m8n8.x2.shared.b16 {%0,%1}, [%2];"
                 : "=r"(r0), "=r"(r1) : "r"(addr));
}
static __device__ __forceinline__ uint32_t smem_u32(const void* p) {
    return (uint32_t)__cvta_generic_to_shared(p);
}
static __device__ __forceinline__ void cp16(uint32_t dst, const void* src) {
    asm volatile("cp.async.ca.shared.global [%0], [%1], 16;" :: "r"(dst), "l"(src) : "memory");
}
#define CP_COMMIT() asm volatile("cp.async.commit_group;" ::: "memory")
#define CP_WAIT1()  asm volatile("cp.async.wait_group 1;" ::: "memory")
#define CP_WAIT0()  asm volatile("cp.async.wait_group 0;" ::: "memory")

// ---------------- kernel 1: norms + operand prep (fused) ----------------
// y=0 (v1): g_r1 + g_A = fp16(v1).  y=1 (v2): g_B = fp16(v2 * w_l^2 * r2).
// l unrolled x4 for independent shfl-reduction chains (shfl latency cover).
__global__ void prep_kernel(const float* __restrict__ v1, const float* __restrict__ v2,
                            const float* __restrict__ w) {
    const int which = blockIdx.y;
    const float* v  = which ? v2 : v1;
    const int gwarp = (blockIdx.x * blockDim.x + threadIdx.x) >> 5;
    const int lane  = threadIdx.x & 31;
    if (gwarp >= B_ * S_) return;

    const float4 xv = ((const float4*)(v + (size_t)gwarp * H_))[lane];

    if (!which) {
        uint2 o;
        o.x = f16x2(xv.x, xv.y);
        o.y = f16x2(xv.z, xv.w);
        *(uint2*)&g_A[(size_t)gwarp * H_ + lane * 4] = o;
    }
    const int b = gwarp >> 9;
    const int s = gwarp & (S_ - 1);

    #pragma unroll
    for (int l = 0; l < L_; l += 4) {
        float4 wv[4];
        float  p[4];
        #pragma unroll
        for (int q = 0; q < 4; ++q) {
            wv[q] = ((const float4*)(w + (l + q) * H_))[lane];
            float t;
            t = wv[q].x * xv.x; p[q]  = t * t;
            t = wv[q].y * xv.y; p[q] += t * t;
            t = wv[q].z * xv.z; p[q] += t * t;
            t = wv[q].w * xv.w; p[q] += t * t;
        }
        #pragma unroll
        for (int o = 16; o; o >>= 1) {
            #pragma unroll
            for (int q = 0; q < 4; ++q)
                p[q] += __shfl_xor_sync(0xffffffffu, p[q], o);
        }
        float r[4];
        #pragma unroll
        for (int q = 0; q < 4; ++q) r[q] = rsqrtf(fmaxf(p[q], 1e-24f));

        if (!which) {
            if (lane == 0) {
                #pragma unroll
                for (int q = 0; q < 4; ++q)
                    g_r1[((size_t)b * L_ + l + q) * S_ + s] = r[q];
            }
        } else {
            #pragma unroll
            for (int q = 0; q < 4; ++q) {
                uint2 o;
                o.x = f16x2(xv.x * wv[q].x * wv[q].x * r[q], xv.y * wv[q].y * wv[q].y * r[q]);
                o.y = f16x2(xv.z * wv[q].z * wv[q].z * r[q], xv.w * wv[q].w * wv[q].w * r[q]);
                *(uint2*)&g_B[((size_t)gwarp * L_ + l + q) * H_ + lane * 4] = o;
            }
        }
    }
}

// ---------------- kernel 2: fp16 GEMM, 3-deep ring, 1 sync/chunk ----------------
// 8 warps: warp_m = wid>>1 (4 x 32 rows), warp_n = wid&1 (2 x 40 cols).
// Ring: chunk c reads buf c%3; prefetch (c+2) -> buf (c+2)%3, last read in
// chunk c-1 and ordered by this chunk's top sync -> no post-K-loop barrier.
__global__ void __launch_bounds__(256, 2)
match_kernel(float* __restrict__ out) {
    extern __shared__ char smc[];
    __half* sm  = (__half*)smc;
    float*  sR1 = (float*)(smc + OFFH_R1 * 2);   // [128][R1STR] r1 transposed

    const int tid  = threadIdx.x;
    const int wid  = tid >> 5;
    const int lane = tid & 31;
    const int b    = blockIdx.z;
    const int s0   = blockIdx.x * TM;            // s fastest: co-resident CTAs share B in L2
    const int t0   = blockIdx.y * TT;

    const int warp_m = wid >> 1;   // 0..3
    const int warp_n = wid & 1;    // 0..1
    const int grp    = lane >> 2;  // 0..7
    const int thr4   = lane & 3;   // 0..3

    const uint32_t sm_u = smem_u32(sm);
    const __half* gA = g_A + ((size_t)b * S_ + s0) * H_;

    // ---- cp.async: A tile (group 0, with chunk 0) ----
    #pragma unroll
    for (int k = 0; k < 8; ++k) {
        const int task = tid + k * 256;          // 2048 x 16B
        const int r = task >> 4, seg = task & 15;
        cp16(sm_u + (uint32_t)(r * STRDH + seg * 8) * 2u, gA + r * H_ + seg * 8);
    }
    auto issue_chunk = [&](int c) {
        const __half* src = g_B + (size_t)(b * S_ + t0 + c * 4) * L_ * H_;   // 80 contiguous rows
        const uint32_t dst = sm_u + (uint32_t)(OFFH_B0 + (c % 3) * NH_BUF) * 2u;
        #pragma unroll
        for (int k = 0; k < 5; ++k) {
            const int task = tid + k * 256;      // 1280 x 16B
            const int r = task >> 4, seg = task & 15;
            cp16(dst + (uint32_t)(r * STRDH + seg * 8) * 2u, src + r * H_ + seg * 8);
        }
    };
    issue_chunk(0);
    CP_COMMIT();                                  // group 0 = A + chunk0
    issue_chunk(1);
    CP_COMMIT();                                  // group 1 = chunk1

    // r1 -> smem transposed [row][l]
    for (int i = tid; i < TM * L_; i += 256) {
        const int l = i >> 7, r = i & 127;
        sR1[r * R1STR + l] = g_r1[((size_t)b * L_ + l) * S_ + s0 + r];
    }

    // ldmatrix base addresses (buffer-relative for B)
    uint32_t a_base[2];
    #pragma unroll
    for (int i = 0; i < 2; ++i) {
        const int row = warp_m * 32 + i * 16 + (lane & 15);
        a_base[i] = sm_u + (uint32_t)(row * STRDH + ((lane >> 4) << 3)) * 2u;
    }
    uint32_t b_off[2];
    #pragma unroll
    for (int jp = 0; jp < 2; ++jp) {
        const int row = warp_n * 40 + jp * 16 + (lane & 7) + ((lane >> 4) << 3);
        b_off[jp] = (uint32_t)(row * STRDH + (((lane >> 3) & 1) << 3)) * 2u;
    }
    const uint32_t b_off4 =
        (uint32_t)((warp_n * 40 + 32 + (lane & 7)) * STRDH + (((lane >> 3) & 1) << 3)) * 2u;

    const size_t bS = (size_t)b * S_;

    #pragma unroll 1
    for (int chunk = 0; chunk < NCHUNKS; ++chunk) {
        if (chunk >= NCHUNKS - 2) { CP_WAIT0(); } else { CP_WAIT1(); }
        __syncthreads();   // chunk's buffer visible; prior reads of (c+2)%3 retired

        if (chunk + 2 < NCHUNKS) {               // prefetch overlaps K-loop + epilogue
            issue_chunk(chunk + 2);
            CP_COMMIT();
        }

        const uint32_t bb = sm_u + (uint32_t)(OFFH_B0 + (chunk % 3) * NH_BUF) * 2u;
        float acc[2][5][4];
        #pragma unroll
        for (int i = 0; i < 2; ++i)
            #pragma unroll
            for (int j = 0; j < 5; ++j)
                #pragma unroll
                for (int q = 0; q < 4; ++q) acc[i][j][q] = 0.f;

        #pragma unroll
        for (int k16 = 0; k16 < 8; ++k16) {
            const uint32_t koff = (uint32_t)(k16 * 32);
            uint32_t af[2][4];
            ldsm4(af[0][0], af[0][1], af[0][2], af[0][3], a_base[0] + koff);
            ldsm4(af[1][0], af[1][1], af[1][2], af[1][3], a_base[1] + koff);
            uint32_t bf[5][2];
            ldsm4(bf[0][0], bf[0][1], bf[1][0], bf[1][1], bb + b_off[0] + koff);
            ldsm4(bf[2][0], bf[2][1], bf[3][0], bf[3][1], bb + b_off[1] + koff);
            ldsm2(bf[4][0], bf[4][1], bb + b_off4 + koff);
            #pragma unroll
            for (int i = 0; i < 2; ++i)
                #pragma unroll
                for (int j = 0; j < 5; ++j)
                    mma_f16(acc[i][j][0], acc[i][j][1], acc[i][j][2], acc[i][j][3],
                            af[i][0], af[i][1], af[i][2], af[i][3], bf[j][0], bf[j][1]);
        }

        // ---- epilogue: out = acc * r1[l,row]; no trailing barrier needed ----
        #pragma unroll
        for (int i = 0; i < 2; ++i) {
            const int rowl = warp_m * 32 + i * 16 + grp;
            float* orow0 = out + ((bS + s0 + rowl) * S_ + t0 + chunk * 4) * L_;
            float* orow1 = orow0 + (size_t)8 * S_ * L_;
            #pragma unroll
            for (int j = 0; j < 5; ++j) {
                const int c = warp_n * 40 + j * 8 + 2 * thr4;  // c = ts*20 + l, l even
                const int l = c - (c / 20) * 20;
                const float2 ra = *(const float2*)&sR1[rowl * R1STR + l];
                const float2 rb = *(const float2*)&sR1[(rowl + 8) * R1STR + l];
                float2 v0, v1r;
                v0.x  = acc[i][j][0] * ra.x;  v0.y  = acc[i][j][1] * ra.y;
                v1r.x = acc[i][j][2] * rb.x;  v1r.y = acc[i][j][3] * rb.y;
                *(float2*)(orow0 + c) = v0;    // out offset within row == c
                *(float2*)(orow1 + c) = v1r;
            }
        }
    }
}

// ---------------- launch ----------------
extern "C" void kernel_launch(void* const* d_in, const int* in_sizes, int n_in,
                              void* d_out, int out_size) {
    (void)in_sizes; (void)n_in; (void)out_size;
    const float* v1 = (const float*)d_in[0];   // (16, 512, 128)
    const float* v2 = (const float*)d_in[1];   // (16, 512, 128)
    const float* w  = (const float*)d_in[2];   // (20, 128)
    float* out = (float*)d_out;                // (16, 512, 512, 20)

    cudaFuncSetAttribute(match_kernel, cudaFuncAttributeMaxDynamicSharedMemorySize, SMEM_BYTES);

    dim3 pgrid((B_ * S_ * 32) / 256, 2);       // y=0: v1/r1/A, y=1: v2 -> B
    prep_kernel<<<pgrid, 256>>>(v1, v2, w);

    dim3 grid(S_ / TM, S_ / TT, B_);           // (4, 16, 16) = 1024 CTAs; s fastest
    match_kernel<<<grid, 256, SMEM_BYTES>>>(out);
}

// round 16
// speedup vs baseline: 1.2440x; 1.0382x over previous
#include <cuda_runtime.h>
#include <cuda_fp16.h>
#include <cstdint>

#define B_   16
#define S_   512
#define H_   128
#define L_   20
#define TM   128          // s per CTA
#define TT   32           // t per CTA  (2 CTAs per SM)
#define NCHUNKS 8         // 4 t x 20 l = 80 N rows per chunk
#define NROWS 80
#define STRDH 136         // smem row stride (halves): 272B, conflict-free ldmatrix
#define R1STR 22          // r1 smem stride (floats)

// smem halves layout: A + 3-deep B ring + r1
#define NH_A   (TM * STRDH)            // 17408
#define NH_BUF (NROWS * STRDH)         // 10880 per buffer
#define OFFH_B0 NH_A
#define OFFH_R1 (NH_A + 3 * NH_BUF)    // 50048 halves -> byte 100096 (16-aligned)
#define SMEM_BYTES (OFFH_R1 * 2 + TM * R1STR * 4)   // 111360 -> 2 CTAs/SM

// precomputed operands in HBM
__device__ __half g_A[B_ * S_ * H_];              // fp16(v1)                2 MB
__device__ __half g_B[(size_t)B_ * S_ * L_ * H_]; // fp16(v2 * w^2 * r2)  41.9 MB
__device__ float  g_r1[B_ * L_ * S_];

static __device__ __forceinline__ uint32_t f16x2(float lo, float hi) {
    uint32_t r;
    asm("cvt.rn.f16x2.f32 %0, %1, %2;" : "=r"(r) : "f"(hi), "f"(lo));
    return r;
}
static __device__ __forceinline__ void mma_f16(float& c0, float& c1, float& c2, float& c3,
                                               uint32_t a0, uint32_t a1, uint32_t a2, uint32_t a3,
                                               uint32_t b0, uint32_t b1) {
    asm volatile("mma.sync.aligned.m16n8k16.row.col.f32.f16.f16.f32 "
                 "{%0,%1,%2,%3}, {%4,%5,%6,%7}, {%8,%9}, {%0,%1,%2,%3};"
                 : "+f"(c0), "+f"(c1), "+f"(c2), "+f"(c3)
                 : "r"(a0), "r"(a1), "r"(a2), "r"(a3), "r"(b0), "r"(b1));
}
static __device__ __forceinline__ void ldsm4(uint32_t& r0, uint32_t& r1, uint32_t& r2, uint32_t& r3,
                                             uint32_t addr) {
    asm volatile("ldmatrix.sync.aligned.m8n8.x4.shared.b16 {%0,%1,%2,%3}, [%4];"
                 : "=r"(r0), "=r"(r1), "=r"(r2), "=r"(r3) : "r"(addr));
}
static __device__ __forceinline__ void ldsm2(uint32_t& r0, uint32_t& r1, uint32_t addr) {
    asm volatile("ldmatrix.sync.aligned.m8n8.x2.shared.b16 {%0,%1}, [%2];"
                 : "=r"(r0), "=r"(r1) : "r"(addr));
}
static __device__ __forceinline__ uint32_t smem_u32(const void* p) {
    return (uint32_t)__cvta_generic_to_shared(p);
}
static __device__ __forceinline__ void cp16cg(uint32_t dst, const void* src) {
    asm volatile("cp.async.cg.shared.global [%0], [%1], 16;" :: "r"(dst), "l"(src) : "memory");
}
static __device__ __forceinline__ void cp16ca(uint32_t dst, const void* src) {
    asm volatile("cp.async.ca.shared.global [%0], [%1], 16;" :: "r"(dst), "l"(src) : "memory");
}
#define CP_COMMIT() asm volatile("cp.async.commit_group;" ::: "memory")
#define CP_WAIT1()  asm volatile("cp.async.wait_group 1;" ::: "memory")
#define CP_WAIT0()  asm volatile("cp.async.wait_group 0;" ::: "memory")

// ---------------- kernel 1: norms + operand prep (fused) ----------------
__global__ void prep_kernel(const float* __restrict__ v1, const float* __restrict__ v2,
                            const float* __restrict__ w) {
    const int which = blockIdx.y;
    const float* v  = which ? v2 : v1;
    const int gwarp = (blockIdx.x * blockDim.x + threadIdx.x) >> 5;
    const int lane  = threadIdx.x & 31;
    if (gwarp >= B_ * S_) return;

    const float4 xv = ((const float4*)(v + (size_t)gwarp * H_))[lane];

    if (!which) {
        uint2 o;
        o.x = f16x2(xv.x, xv.y);
        o.y = f16x2(xv.z, xv.w);
        *(uint2*)&g_A[(size_t)gwarp * H_ + lane * 4] = o;
    }
    const int b = gwarp >> 9;
    const int s = gwarp & (S_ - 1);

    #pragma unroll
    for (int l = 0; l < L_; l += 4) {
        float4 wv[4];
        float  p[4];
        #pragma unroll
        for (int q = 0; q < 4; ++q) {
            wv[q] = ((const float4*)(w + (l + q) * H_))[lane];
            float t;
            t = wv[q].x * xv.x; p[q]  = t * t;
            t = wv[q].y * xv.y; p[q] += t * t;
            t = wv[q].z * xv.z; p[q] += t * t;
            t = wv[q].w * xv.w; p[q] += t * t;
        }
        #pragma unroll
        for (int o = 16; o; o >>= 1) {
            #pragma unroll
            for (int q = 0; q < 4; ++q)
                p[q] += __shfl_xor_sync(0xffffffffu, p[q], o);
        }
        float r[4];
        #pragma unroll
        for (int q = 0; q < 4; ++q) r[q] = rsqrtf(fmaxf(p[q], 1e-24f));

        if (!which) {
            if (lane == 0) {
                #pragma unroll
                for (int q = 0; q < 4; ++q)
                    g_r1[((size_t)b * L_ + l + q) * S_ + s] = r[q];
            }
        } else {
            #pragma unroll
            for (int q = 0; q < 4; ++q) {
                uint2 o;
                o.x = f16x2(xv.x * wv[q].x * wv[q].x * r[q], xv.y * wv[q].y * wv[q].y * r[q]);
                o.y = f16x2(xv.z * wv[q].z * wv[q].z * r[q], xv.w * wv[q].w * wv[q].w * r[q]);
                *(uint2*)&g_B[((size_t)gwarp * L_ + l + q) * H_ + lane * 4] = o;
            }
        }
    }
}

// ---------------- kernel 2: fp16 GEMM, shuffle-paired STG.128 epilogue ----------------
// 8 warps: warp_m = wid>>1 (4 x 32 rows), warp_n = wid&1 (2 x 40 cols).
// 3-deep B ring, 1 sync/chunk. Epilogue packs n8-tile pairs into 16-col
// float4 runs via 8 SHFLs -> STG.128 (512B/inst over 8 lines vs 256B).
__global__ void __launch_bounds__(256, 2)
match_kernel(float* __restrict__ out) {
    extern __shared__ char smc[];
    __half* sm  = (__half*)smc;
    float*  sR1 = (float*)(smc + OFFH_R1 * 2);   // [128][R1STR] r1 transposed

    const int tid  = threadIdx.x;
    const int wid  = tid >> 5;
    const int lane = tid & 31;
    const int b    = blockIdx.z;
    const int s0   = blockIdx.x * TM;
    const int t0   = blockIdx.y * TT;

    const int warp_m = wid >> 1;   // 0..3
    const int warp_n = wid & 1;    // 0..1
    const int grp    = lane >> 2;  // 0..7
    const int thr4   = lane & 3;   // 0..3

    const uint32_t sm_u = smem_u32(sm);
    const __half* gA = g_A + ((size_t)b * S_ + s0) * H_;

    // ---- cp.async: A tile (group 0, with chunk 0) ----
    #pragma unroll
    for (int k = 0; k < 8; ++k) {
        const int task = tid + k * 256;
        const int r = task >> 4, seg = task & 15;
        cp16ca(sm_u + (uint32_t)(r * STRDH + seg * 8) * 2u, gA + r * H_ + seg * 8);
    }
    auto issue_chunk = [&](int c) {
        const __half* src = g_B + (size_t)(b * S_ + t0 + c * 4) * L_ * H_;
        const uint32_t dst = sm_u + (uint32_t)(OFFH_B0 + (c % 3) * NH_BUF) * 2u;
        #pragma unroll
        for (int k = 0; k < 5; ++k) {
            const int task = tid + k * 256;
            const int r = task >> 4, seg = task & 15;
            cp16cg(dst + (uint32_t)(r * STRDH + seg * 8) * 2u, src + r * H_ + seg * 8);
        }
    };
    issue_chunk(0);
    CP_COMMIT();
    issue_chunk(1);
    CP_COMMIT();

    for (int i = tid; i < TM * L_; i += 256) {
        const int l = i >> 7, r = i & 127;
        sR1[r * R1STR + l] = g_r1[((size_t)b * L_ + l) * S_ + s0 + r];
    }

    uint32_t a_base[2];
    #pragma unroll
    for (int i = 0; i < 2; ++i) {
        const int row = warp_m * 32 + i * 16 + (lane & 15);
        a_base[i] = sm_u + (uint32_t)(row * STRDH + ((lane >> 4) << 3)) * 2u;
    }
    uint32_t b_off[2];
    #pragma unroll
    for (int jp = 0; jp < 2; ++jp) {
        const int row = warp_n * 40 + jp * 16 + (lane & 7) + ((lane >> 4) << 3);
        b_off[jp] = (uint32_t)(row * STRDH + (((lane >> 3) & 1) << 3)) * 2u;
    }
    const uint32_t b_off4 =
        (uint32_t)((warp_n * 40 + 32 + (lane & 7)) * STRDH + (((lane >> 3) & 1) << 3)) * 2u;

    const size_t bS = (size_t)b * S_;
    const int srcLo = (grp << 2) | ((thr4 & 1) << 1);   // shuffle sources (same grp)
    const int srcHi = srcLo + 1;
    const bool selB = (thr4 >> 1) != 0;                 // tile 2p+1 for t>=2

    #pragma unroll 1
    for (int chunk = 0; chunk < NCHUNKS; ++chunk) {
        if (chunk >= NCHUNKS - 2) { CP_WAIT0(); } else { CP_WAIT1(); }
        __syncthreads();

        if (chunk + 2 < NCHUNKS) {
            issue_chunk(chunk + 2);
            CP_COMMIT();
        }

        const uint32_t bb = sm_u + (uint32_t)(OFFH_B0 + (chunk % 3) * NH_BUF) * 2u;
        float acc[2][5][4];
        #pragma unroll
        for (int i = 0; i < 2; ++i)
            #pragma unroll
            for (int j = 0; j < 5; ++j)
                #pragma unroll
                for (int q = 0; q < 4; ++q) acc[i][j][q] = 0.f;

        #pragma unroll
        for (int k16 = 0; k16 < 8; ++k16) {
            const uint32_t koff = (uint32_t)(k16 * 32);
            uint32_t af[2][4];
            ldsm4(af[0][0], af[0][1], af[0][2], af[0][3], a_base[0] + koff);
            ldsm4(af[1][0], af[1][1], af[1][2], af[1][3], a_base[1] + koff);
            uint32_t bf[5][2];
            ldsm4(bf[0][0], bf[0][1], bf[1][0], bf[1][1], bb + b_off[0] + koff);
            ldsm4(bf[2][0], bf[2][1], bf[3][0], bf[3][1], bb + b_off[1] + koff);
            ldsm2(bf[4][0], bf[4][1], bb + b_off4 + koff);
            #pragma unroll
            for (int i = 0; i < 2; ++i)
                #pragma unroll
                for (int j = 0; j < 5; ++j)
                    mma_f16(acc[i][j][0], acc[i][j][1], acc[i][j][2], acc[i][j][3],
                            af[i][0], af[i][1], af[i][2], af[i][3], bf[j][0], bf[j][1]);
        }

        // ---- epilogue: scale by r1, shuffle-pair, STG.128 ----
        #pragma unroll
        for (int i = 0; i < 2; ++i) {
            const int rowl = warp_m * 32 + i * 16 + grp;
            float* orow0 = out + ((bS + s0 + rowl) * S_ + t0 + chunk * 4) * L_;
            float* orow1 = orow0 + (size_t)8 * S_ * L_;

            float2 v0[5], v1r[5];
            #pragma unroll
            for (int j = 0; j < 5; ++j) {
                const int c = warp_n * 40 + j * 8 + 2 * thr4;  // c = ts*20 + l, l even
                const int l = c - (c / 20) * 20;
                const float2 ra = *(const float2*)&sR1[rowl * R1STR + l];
                const float2 rb = *(const float2*)&sR1[(rowl + 8) * R1STR + l];
                v0[j].x  = acc[i][j][0] * ra.x;  v0[j].y  = acc[i][j][1] * ra.y;
                v1r[j].x = acc[i][j][2] * rb.x;  v1r[j].y = acc[i][j][3] * rb.y;
            }
            #pragma unroll
            for (int p = 0; p < 2; ++p) {
                // h = 0 (row rowl)
                {
                    float ax = __shfl_sync(0xffffffffu, v0[2*p].x,   srcLo);
                    float ay = __shfl_sync(0xffffffffu, v0[2*p].y,   srcLo);
                    float bx = __shfl_sync(0xffffffffu, v0[2*p+1].x, srcLo);
                    float by = __shfl_sync(0xffffffffu, v0[2*p+1].y, srcLo);
                    float4 o;
                    o.x = selB ? bx : ax;  o.y = selB ? by : ay;
                    ax = __shfl_sync(0xffffffffu, v0[2*p].x,   srcHi);
                    ay = __shfl_sync(0xffffffffu, v0[2*p].y,   srcHi);
                    bx = __shfl_sync(0xffffffffu, v0[2*p+1].x, srcHi);
                    by = __shfl_sync(0xffffffffu, v0[2*p+1].y, srcHi);
                    o.z = selB ? bx : ax;  o.w = selB ? by : ay;
                    *(float4*)(orow0 + warp_n * 40 + p * 16 + 4 * thr4) = o;
                }
                // h = 1 (row rowl+8)
                {
                    float ax = __shfl_sync(0xffffffffu, v1r[2*p].x,   srcLo);
                    float ay = __shfl_sync(0xffffffffu, v1r[2*p].y,   srcLo);
                    float bx = __shfl_sync(0xffffffffu, v1r[2*p+1].x, srcLo);
                    float by = __shfl_sync(0xffffffffu, v1r[2*p+1].y, srcLo);
                    float4 o;
                    o.x = selB ? bx : ax;  o.y = selB ? by : ay;
                    ax = __shfl_sync(0xffffffffu, v1r[2*p].x,   srcHi);
                    ay = __shfl_sync(0xffffffffu, v1r[2*p].y,   srcHi);
                    bx = __shfl_sync(0xffffffffu, v1r[2*p+1].x, srcHi);
                    by = __shfl_sync(0xffffffffu, v1r[2*p+1].y, srcHi);
                    o.z = selB ? bx : ax;  o.w = selB ? by : ay;
                    *(float4*)(orow1 + warp_n * 40 + p * 16 + 4 * thr4) = o;
                }
            }
            // leftover 5th n8-tile (cols 32..39): direct float2
            *(float2*)(orow0 + warp_n * 40 + 32 + 2 * thr4) = v0[4];
            *(float2*)(orow1 + warp_n * 40 + 32 + 2 * thr4) = v1r[4];
        }
    }
}

// ---------------- launch ----------------
extern "C" void kernel_launch(void* const* d_in, const int* in_sizes, int n_in,
                              void* d_out, int out_size) {
    (void)in_sizes; (void)n_in; (void)out_size;
    const float* v1 = (const float*)d_in[0];   // (16, 512, 128)
    const float* v2 = (const float*)d_in[1];   // (16, 512, 128)
    const float* w  = (const float*)d_in[2];   // (20, 128)
    float* out = (float*)d_out;                // (16, 512, 512, 20)

    cudaFuncSetAttribute(match_kernel, cudaFuncAttributeMaxDynamicSharedMemorySize, SMEM_BYTES);

    dim3 pgrid((B_ * S_ * 32) / 256, 2);       // y=0: v1/r1/A, y=1: v2 -> B
    prep_kernel<<<pgrid, 256>>>(v1, v2, w);

    dim3 grid(S_ / TM, S_ / TT, B_);           // (4, 16, 16) = 1024 CTAs; s fastest
    match_kernel<<<grid, 256, SMEM_BYTES>>>(out);
}